// round 15
// baseline (speedup 1.0000x reference)
#include <cuda_runtime.h>
#include <math.h>
#include <stdint.h>

#define DM   512
#define LSEQ 256
#define BB   2
#define HH   8
#define DK   64
#define BH   16
#define BL   512
#define NEG_BIG -1.0e30f
#define POS_BIG  1.0e30f

typedef unsigned long long ull;

// ---------------- scratch (device globals; no allocations allowed) -----------
__device__ float2 g_xs[BL * DM];     // tf32-split {hi,lo} of x
__device__ float2 g_wqs[DM * DM];
__device__ float2 g_wks[DM * DM];
__device__ float2 g_wvs[DM * DM];
__device__ float2 g_wos[DM * DM];
__device__ float2 g_ctxs[BL * DM];   // split ctx (written by k_ctxfin)
__device__ float  g_pp[6 * BL * DM]; // proj partials (3 gemms x splitK=2)
__device__ float  g_op[4 * BL * DM]; // out partials (splitK=4)
__device__ float  g_cp[8 * BH * LSEQ * DK]; // ctx partials (8 j-tiles)
__device__ float  g_Q[BH * LSEQ * DK];
__device__ float  g_K[BH * LSEQ * DK];
__device__ float  g_V[BH * LSEQ * DK];

// ---------------- helpers -----------------------------------------------------
__device__ __forceinline__ float tf32r(float x) {
    uint32_t u;
    asm("cvt.rna.tf32.f32 %0, %1;" : "=r"(u) : "f"(x));
    return __uint_as_float(u);
}
__device__ __forceinline__ void mma_tf32(float* d, const uint32_t* a, const uint32_t* b) {
    asm volatile(
        "mma.sync.aligned.m16n8k8.row.col.f32.tf32.tf32.f32 "
        "{%0,%1,%2,%3}, {%4,%5,%6,%7}, {%8,%9}, {%0,%1,%2,%3};"
        : "+f"(d[0]), "+f"(d[1]), "+f"(d[2]), "+f"(d[3])
        : "r"(a[0]), "r"(a[1]), "r"(a[2]), "r"(a[3]), "r"(b[0]), "r"(b[1]));
}
__device__ __forceinline__ void cpasync16(uint32_t dst, const void* src) {
    asm volatile("cp.async.cg.shared.global [%0], [%1], 16;" :: "r"(dst), "l"(src));
}
__device__ __forceinline__ ull pk2(float lo, float hi) {
    ull r;
    asm("mov.b64 %0, {%1, %2};" : "=l"(r) : "f"(lo), "f"(hi));
    return r;
}
__device__ __forceinline__ void upk2(ull v, float& lo, float& hi) {
    asm("mov.b64 {%0, %1}, %2;" : "=f"(lo), "=f"(hi) : "l"(v));
}
__device__ __forceinline__ ull add2(ull a, ull b) {
    ull r;
    asm("add.rn.f32x2 %0, %1, %2;" : "=l"(r) : "l"(a), "l"(b));
    return r;
}

// ---------------- prepass: tf32 split of x and the 4 weight matrices ----------
__global__ __launch_bounds__(256) void k_split(const float* __restrict__ x,
                                               const float* __restrict__ Wq,
                                               const float* __restrict__ Wk,
                                               const float* __restrict__ Wv,
                                               const float* __restrict__ Wo)
{
    const float* src;
    float2* dst;
    switch (blockIdx.y) {
        case 0: src = x;  dst = g_xs;  break;
        case 1: src = Wq; dst = g_wqs; break;
        case 2: src = Wk; dst = g_wks; break;
        case 3: src = Wv; dst = g_wvs; break;
        default: src = Wo; dst = g_wos; break;
    }
    const int base = (blockIdx.x * 256 + threadIdx.x) * 8;
#pragma unroll
    for (int t = 0; t < 2; t++) {
        const float4 v = *(const float4*)&src[base + t * 4];
        const float h0 = tf32r(v.x), h1 = tf32r(v.y), h2 = tf32r(v.z), h3 = tf32r(v.w);
        float4* d4 = (float4*)&dst[base + t * 4];
        d4[0] = make_float4(h0, tf32r(v.x - h0), h1, tf32r(v.y - h1));
        d4[1] = make_float4(h2, tf32r(v.z - h2), h3, tf32r(v.w - h3));
    }
}

// ---------------- TC GEMM: split-tf32 3-mma, 2-stage cp.async pipeline -------
// 32KB smem -> 3 blocks/SM: proj (384 blocks) runs in one wave.
__global__ __launch_bounds__(256, 3) void k_gemm_tc(int mode)
{
    __shared__ float As[2][64 * 32];   // 8KB per stage
    __shared__ float Bs[2][64 * 32];

    const int z = blockIdx.z;
    const int gemm = (mode == 0) ? (z >> 1) : 0;
    const int zk   = (mode == 0) ? (z & 1) : z;
    const int k0   = (mode == 0) ? zk * 256 : zk * 128;
    const int nc   = (mode == 0) ? 16 : 8;
    const float2* Xs = (mode == 0) ? g_xs : g_ctxs;
    const float2* Ws = (mode == 0)
        ? ((gemm == 0) ? g_wqs : ((gemm == 1) ? g_wks : g_wvs)) : g_wos;
    float* Y = (mode == 0) ? (g_pp + z * (BL * DM)) : (g_op + z * (BL * DM));

    const int bm = blockIdx.y, bn = blockIdx.x;
    const int tid = threadIdx.x;
    const int wid = tid >> 5, lane = tid & 31;
    const int m0 = (wid & 3) * 16;
    const int n0 = (wid >> 2) * 32;
    const int g = lane >> 2, cc = lane & 3;
    const int sw = (g & 3) << 2;

    const int lrow = tid >> 2, lq = tid & 3;
    const int usw0 = (lq) ^ ((lrow & 3) << 1);
    const int usw1 = (lq + 4) ^ ((lrow & 3) << 1);
    const float2* Xrow = &Xs[(bm * 64 + lrow) * DM + k0];
    const float2* Wrow = &Ws[(bn * 64 + lrow) * DM + k0];
    const uint32_t asb = (uint32_t)__cvta_generic_to_shared(&As[0][0]);
    const uint32_t bsb = (uint32_t)__cvta_generic_to_shared(&Bs[0][0]);

#define ISSUE_CHUNK(CH, BUF) do {                                            \
        const uint32_t ab = asb + (BUF) * 8192 + lrow * 128;                 \
        const uint32_t bb = bsb + (BUF) * 8192 + lrow * 128;                 \
        cpasync16(ab + usw0 * 16, Xrow + (CH) * 16 + lq * 2);                \
        cpasync16(ab + usw1 * 16, Xrow + (CH) * 16 + (lq + 4) * 2);          \
        cpasync16(bb + usw0 * 16, Wrow + (CH) * 16 + lq * 2);                \
        cpasync16(bb + usw1 * 16, Wrow + (CH) * 16 + (lq + 4) * 2);          \
        asm volatile("cp.async.commit_group;");                              \
    } while (0)

    float acc[4][4];
#pragma unroll
    for (int nt = 0; nt < 4; nt++)
#pragma unroll
        for (int e = 0; e < 4; e++) acc[nt][e] = 0.0f;

    ISSUE_CHUNK(0, 0);

    for (int ch = 0; ch < nc; ch++) {
        if (ch + 1 < nc) {
            ISSUE_CHUNK(ch + 1, (ch + 1) & 1);
            asm volatile("cp.async.wait_group 1;");
        } else {
            asm volatile("cp.async.wait_group 0;");
        }
        __syncthreads();

        const float* Ab = As[ch & 1];
        const float* Bb = Bs[ch & 1];
#pragma unroll
        for (int ks = 0; ks < 2; ks++) {
            const int kb = ks * 8;
            const float2 a0 = *(const float2*)&Ab[(m0 + g) * 32 + 2 * ((kb + cc) ^ sw)];
            const float2 a1 = *(const float2*)&Ab[(m0 + g + 8) * 32 + 2 * ((kb + cc) ^ sw)];
            const float2 a2 = *(const float2*)&Ab[(m0 + g) * 32 + 2 * ((kb + cc + 4) ^ sw)];
            const float2 a3 = *(const float2*)&Ab[(m0 + g + 8) * 32 + 2 * ((kb + cc + 4) ^ sw)];
            const uint32_t ahi[4] = {__float_as_uint(a0.x), __float_as_uint(a1.x),
                                     __float_as_uint(a2.x), __float_as_uint(a3.x)};
            const uint32_t alo[4] = {__float_as_uint(a0.y), __float_as_uint(a1.y),
                                     __float_as_uint(a2.y), __float_as_uint(a3.y)};
#pragma unroll
            for (int nt = 0; nt < 4; nt++) {
                const int rn = n0 + nt * 8 + g;
                const float2 b0 = *(const float2*)&Bb[rn * 32 + 2 * ((kb + cc) ^ sw)];
                const float2 b1 = *(const float2*)&Bb[rn * 32 + 2 * ((kb + cc + 4) ^ sw)];
                const uint32_t bhi[2] = {__float_as_uint(b0.x), __float_as_uint(b1.x)};
                const uint32_t blo[2] = {__float_as_uint(b0.y), __float_as_uint(b1.y)};
                mma_tf32(acc[nt], ahi, bhi);
                mma_tf32(acc[nt], ahi, blo);
                mma_tf32(acc[nt], alo, bhi);
            }
        }
        __syncthreads();
    }

    const int row0 = bm * 64 + m0 + g;
#pragma unroll
    for (int nt = 0; nt < 4; nt++) {
        const int col = bn * 64 + n0 + nt * 8 + cc * 2;
        *(float2*)&Y[row0 * DM + col] = make_float2(acc[nt][0], acc[nt][1]);
        *(float2*)&Y[(row0 + 8) * DM + col] = make_float2(acc[nt][2], acc[nt][3]);
    }
#undef ISSUE_CHUNK
}

// ---------------- tropical linear + partial reduce + activation ---------------
__global__ __launch_bounds__(256) void k_trop(const float* __restrict__ Wqt,
                                              const float* __restrict__ Wkt,
                                              const float* __restrict__ Wvt,
                                              const float* __restrict__ lam)
{
    __shared__ float Wts[64][65];
    __shared__ float ar[16][65];

    const int gemm = blockIdx.z;
    const float* Wt = (gemm == 0) ? Wqt : ((gemm == 1) ? Wkt : Wvt);
    float* out = (gemm == 0) ? g_Q : ((gemm == 1) ? g_K : g_V);
    const int bh = blockIdx.y;
    const int b = bh >> 3, h = bh & 7;
    const int l0 = blockIdx.x * 16;
    const int tid = threadIdx.x;

    for (int idx = tid; idx < 64 * 64; idx += 256) {
        const int o = idx >> 6, i = idx & 63;
        Wts[i][o] = Wt[idx];
    }
    for (int idx = tid; idx < 16 * 64; idx += 256) {
        const int r = idx >> 6, i = idx & 63;
        const int gidx = (b * LSEQ + l0 + r) * DM + h * DK + i;
        const float* p = g_pp + gemm * 2 * (BL * DM) + gidx;
        const float s = p[0] + p[BL * DM];
        ar[r][i] = log1pf(fmaxf(s, 0.0f)) - lam[h * DK + i];
    }
    __syncthreads();

    const int o = tid & 63, rg = tid >> 6;
    float m[4] = {NEG_BIG, NEG_BIG, NEG_BIG, NEG_BIG};
#pragma unroll 8
    for (int i = 0; i < 64; i++) {
        const float wv = Wts[i][o];
#pragma unroll
        for (int rr = 0; rr < 4; rr++)
            m[rr] = fmaxf(m[rr], ar[rg * 4 + rr][i] + wv);
    }
#pragma unroll
    for (int rr = 0; rr < 4; rr++)
        out[(bh * LSEQ + l0 + rg * 4 + rr) * DK + o] = m[rr];
}

// ---------------- fused scores + partial context (32i x 32j tiles) ------------
// Grid (8 it, 8 jt, 16 bh) = 1024 blocks, 256 threads.
// Phase A: per-thread 4i x 1j. Phase B: per-thread 4i x 2d, packed add2 with
// duplicated {s,s} scores stored in the dead Kt buffer.
__global__ __launch_bounds__(256, 5) void k_scores_ctx(float* __restrict__ scores)
{
    __shared__ float Qs[32][68];
    __shared__ float KtSs[64 * 34];  // phase A: Kt[d][j] stride 34; then Sd[j][i] dup-ull stride 33
    __shared__ float Vs[32][68];

    const int it = blockIdx.x, jt = blockIdx.y, bh = blockIdx.z;
    const int i0 = it * 32, j0 = jt * 32;
    const int tid = threadIdx.x;
    const int lane = tid & 31;
    const int w = tid >> 5;
    const int ia = w * 4;            // this thread's 4 i rows
    const int ja = lane;             // phase-A single j col

    // load Q tile (32 x 64)
    {
#pragma unroll
        for (int t = 0; t < 2; t++) {
            const int idx = tid + t * 256;
            const int r = idx >> 4, dq = (idx & 15) * 4;
            *(float4*)&Qs[r][dq] = *(const float4*)&g_Q[(bh * LSEQ + i0 + r) * DK + dq];
        }
    }
    // load K (transposed, 32 j) and V tiles
    {
        const float4* Kp = (const float4*)(g_K + (bh * LSEQ + j0) * DK);
        const float4* Vp = (const float4*)(g_V + (bh * LSEQ + j0) * DK);
#pragma unroll
        for (int t = 0; t < 2; t++) {
            const int idx = tid + t * 256;           // 0..511
            const int j = idx >> 4, d4 = (idx & 15) * 4;
            const float4 kv = Kp[idx];
            KtSs[(d4 + 0) * 34 + j] = kv.x; KtSs[(d4 + 1) * 34 + j] = kv.y;
            KtSs[(d4 + 2) * 34 + j] = kv.z; KtSs[(d4 + 3) * 34 + j] = kv.w;
            *(float4*)&Vs[j][d4] = Vp[idx];
        }
    }
    __syncthreads();

    // ---- phase A: 4i x 1j scores ----
    float s[4];
    {
        float mx[4], mn[4];
#pragma unroll
        for (int a = 0; a < 4; a++) { mx[a] = NEG_BIG; mn[a] = POS_BIG; }
#pragma unroll
        for (int t = 0; t < 16; t++) {
            float4 q[4];
#pragma unroll
            for (int a = 0; a < 4; a++)
                q[a] = *(const float4*)&Qs[ia + a][t * 4];   // broadcast
#pragma unroll
            for (int e = 0; e < 4; e++) {
                const float kd = KtSs[(t * 4 + e) * 34 + ja];   // lane-consecutive
#pragma unroll
                for (int a = 0; a < 4; a++) {
                    const float qe = (e == 0) ? q[a].x : (e == 1) ? q[a].y
                                   : (e == 2) ? q[a].z : q[a].w;
                    const float d = qe - kd;
                    mx[a] = fmaxf(mx[a], d);
                    mn[a] = fminf(mn[a], d);
                }
            }
        }
#pragma unroll
        for (int a = 0; a < 4; a++) {
            s[a] = mn[a] - mx[a];
            scores[(bh * LSEQ + i0 + ia + a) * LSEQ + j0 + ja] = s[a];
        }
    }
    __syncthreads();   // everyone done reading Kt

    // stash duplicated {s,s} into the (dead) Kt buffer: Sd[j][i], ull stride 33
    {
        ull* Sd = (ull*)KtSs;
#pragma unroll
        for (int a = 0; a < 4; a++)
            Sd[ja * 33 + ia + a] = pk2(s[a], s[a]);
    }
    __syncthreads();

    // ---- phase B: 4i x 2d partial context (packed add2) ----
    {
        const int d0 = lane * 2;
        const ull* Sd = (const ull*)KtSs;
        float acc[4][2];
#pragma unroll
        for (int a = 0; a < 4; a++) { acc[a][0] = NEG_BIG; acc[a][1] = NEG_BIG; }

#pragma unroll 4
        for (int j = 0; j < 32; j += 2) {
            const ull v0 = *(const ull*)&Vs[j][d0];
            const ull v1 = *(const ull*)&Vs[j + 1][d0];
#pragma unroll
            for (int a = 0; a < 4; a++) {
                const ull sa = Sd[j * 33 + ia + a];         // broadcast
                const ull sb = Sd[(j + 1) * 33 + ia + a];   // broadcast
                const ull t0 = add2(sa, v0);
                const ull t1 = add2(sb, v1);
                float t0l, t0h, t1l, t1h;
                upk2(t0, t0l, t0h);
                upk2(t1, t1l, t1h);
                acc[a][0] = fmaxf(fmaxf(acc[a][0], t0l), t1l);
                acc[a][1] = fmaxf(fmaxf(acc[a][1], t0h), t1h);
            }
        }

        float* cp = g_cp + jt * (BH * LSEQ * DK) + bh * (LSEQ * DK);
#pragma unroll
        for (int a = 0; a < 4; a++)
            *(float2*)&cp[(i0 + ia + a) * DK + d0] = make_float2(acc[a][0], acc[a][1]);
    }
}

// ---------------- ctx finalize: 8-way max + expm1 + tf32 split ----------------
__global__ __launch_bounds__(256) void k_ctxfin()
{
    const int e2 = blockIdx.x * 256 + threadIdx.x;   // float2 index, 131072 total
    const int e = e2 * 2;
    const int bh = e >> 14;
    const int rem = e & 16383;
    const int l = rem >> 6;
    const int d = rem & 63;
    const int b = bh >> 3, h = bh & 7;

    const float2* p = (const float2*)g_cp;
    float2 m = p[e2];
#pragma unroll
    for (int z = 1; z < 8; z++) {
        const float2 t = p[z * 131072 + e2];
        m.x = fmaxf(m.x, t.x);
        m.y = fmaxf(m.y, t.y);
    }
    const float vx = expm1f(m.x);
    const float vy = expm1f(m.y);
    const float hx = tf32r(vx), hy = tf32r(vy);
    *(float4*)&g_ctxs[(b * LSEQ + l) * DM + h * DK + d] =
        make_float4(hx, tf32r(vx - hx), hy, tf32r(vy - hy));
}

// ---------------- splitK reduce for the output GEMM ---------------------------
__global__ __launch_bounds__(256) void k_reduce(float* __restrict__ out)
{
    const int idx = blockIdx.x * 256 + threadIdx.x;
    const float4* p = (const float4*)g_op;
    float4 s = p[idx];
#pragma unroll
    for (int z = 1; z < 4; z++) {
        const float4 t = p[z * 65536 + idx];
        s.x += t.x; s.y += t.y; s.z += t.z; s.w += t.w;
    }
    ((float4*)out)[idx] = s;
}

// ---------------- launch ------------------------------------------------------
extern "C" void kernel_launch(void* const* d_in, const int* in_sizes, int n_in,
                              void* d_out, int out_size)
{
    const float* x   = (const float*)d_in[0];
    const float* Wq  = (const float*)d_in[1];
    const float* Wk  = (const float*)d_in[2];
    const float* Wv  = (const float*)d_in[3];
    const float* Wo  = (const float*)d_in[4];
    const float* lam = (const float*)d_in[5];
    const float* Wqt = (const float*)d_in[6];
    const float* Wkt = (const float*)d_in[7];
    const float* Wvt = (const float*)d_in[8];
    float* out = (float*)d_out;
    float* scores = out + BL * DM;

    k_split<<<dim3(128, 5), 256>>>(x, Wq, Wk, Wv, Wo);
    k_gemm_tc<<<dim3(8, 8, 6), 256>>>(0);
    k_trop<<<dim3(16, 16, 3), 256>>>(Wqt, Wkt, Wvt, lam);
    k_scores_ctx<<<dim3(8, 8, 16), 256>>>(scores);
    k_ctxfin<<<512, 256>>>();
    k_gemm_tc<<<dim3(8, 8, 4), 256>>>(1);
    k_reduce<<<256, 256>>>(out);
}

// round 16
// speedup vs baseline: 1.0226x; 1.0226x over previous
#include <cuda_runtime.h>
#include <math.h>
#include <stdint.h>

#define DM   512
#define LSEQ 256
#define BB   2
#define HH   8
#define DK   64
#define BH   16
#define BL   512
#define NEG_BIG -1.0e30f
#define POS_BIG  1.0e30f

typedef unsigned long long ull;

// ---------------- scratch (device globals; no allocations allowed) -----------
__device__ float2 g_xs[BL * DM];     // tf32-split {hi,lo} of x
__device__ float2 g_wqs[DM * DM];
__device__ float2 g_wks[DM * DM];
__device__ float2 g_wvs[DM * DM];
__device__ float2 g_wos[DM * DM];
__device__ float2 g_ctxs[BL * DM];   // split ctx (written by k_ctxfin)
__device__ float  g_pp[6 * BL * DM]; // proj partials (3 gemms x splitK=2)
__device__ float  g_op[4 * BL * DM]; // out partials (splitK=4)
__device__ float  g_cp[8 * BH * LSEQ * DK]; // ctx partials (8 j-tiles)
__device__ float  g_Q[BH * LSEQ * DK];
__device__ float  g_K[BH * LSEQ * DK];
__device__ float  g_V[BH * LSEQ * DK];

// ---------------- helpers -----------------------------------------------------
__device__ __forceinline__ float tf32r(float x) {
    uint32_t u;
    asm("cvt.rna.tf32.f32 %0, %1;" : "=r"(u) : "f"(x));
    return __uint_as_float(u);
}
__device__ __forceinline__ void mma_tf32(float* d, const uint32_t* a, const uint32_t* b) {
    asm volatile(
        "mma.sync.aligned.m16n8k8.row.col.f32.tf32.tf32.f32 "
        "{%0,%1,%2,%3}, {%4,%5,%6,%7}, {%8,%9}, {%0,%1,%2,%3};"
        : "+f"(d[0]), "+f"(d[1]), "+f"(d[2]), "+f"(d[3])
        : "r"(a[0]), "r"(a[1]), "r"(a[2]), "r"(a[3]), "r"(b[0]), "r"(b[1]));
}
__device__ __forceinline__ void cpasync16(uint32_t dst, const void* src) {
    asm volatile("cp.async.cg.shared.global [%0], [%1], 16;" :: "r"(dst), "l"(src));
}

// ---------------- prepass: tf32 split of x and the 4 weight matrices ----------
__global__ __launch_bounds__(256) void k_split(const float* __restrict__ x,
                                               const float* __restrict__ Wq,
                                               const float* __restrict__ Wk,
                                               const float* __restrict__ Wv,
                                               const float* __restrict__ Wo)
{
    const float* src;
    float2* dst;
    switch (blockIdx.y) {
        case 0: src = x;  dst = g_xs;  break;
        case 1: src = Wq; dst = g_wqs; break;
        case 2: src = Wk; dst = g_wks; break;
        case 3: src = Wv; dst = g_wvs; break;
        default: src = Wo; dst = g_wos; break;
    }
    const int base = (blockIdx.x * 256 + threadIdx.x) * 8;
#pragma unroll
    for (int t = 0; t < 2; t++) {
        const float4 v = *(const float4*)&src[base + t * 4];
        const float h0 = tf32r(v.x), h1 = tf32r(v.y), h2 = tf32r(v.z), h3 = tf32r(v.w);
        float4* d4 = (float4*)&dst[base + t * 4];
        d4[0] = make_float4(h0, tf32r(v.x - h0), h1, tf32r(v.y - h1));
        d4[1] = make_float4(h2, tf32r(v.z - h2), h3, tf32r(v.w - h3));
    }
}

// ---------------- TC GEMM: split-tf32 3-mma, 2-stage cp.async pipeline -------
__global__ __launch_bounds__(256, 3) void k_gemm_tc(int mode)
{
    __shared__ float As[2][64 * 32];
    __shared__ float Bs[2][64 * 32];

    const int z = blockIdx.z;
    const int gemm = (mode == 0) ? (z >> 1) : 0;
    const int zk   = (mode == 0) ? (z & 1) : z;
    const int k0   = (mode == 0) ? zk * 256 : zk * 128;
    const int nc   = (mode == 0) ? 16 : 8;
    const float2* Xs = (mode == 0) ? g_xs : g_ctxs;
    const float2* Ws = (mode == 0)
        ? ((gemm == 0) ? g_wqs : ((gemm == 1) ? g_wks : g_wvs)) : g_wos;
    float* Y = (mode == 0) ? (g_pp + z * (BL * DM)) : (g_op + z * (BL * DM));

    const int bm = blockIdx.y, bn = blockIdx.x;
    const int tid = threadIdx.x;
    const int wid = tid >> 5, lane = tid & 31;
    const int m0 = (wid & 3) * 16;
    const int n0 = (wid >> 2) * 32;
    const int g = lane >> 2, cc = lane & 3;
    const int sw = (g & 3) << 2;

    const int lrow = tid >> 2, lq = tid & 3;
    const int usw0 = (lq) ^ ((lrow & 3) << 1);
    const int usw1 = (lq + 4) ^ ((lrow & 3) << 1);
    const float2* Xrow = &Xs[(bm * 64 + lrow) * DM + k0];
    const float2* Wrow = &Ws[(bn * 64 + lrow) * DM + k0];
    const uint32_t asb = (uint32_t)__cvta_generic_to_shared(&As[0][0]);
    const uint32_t bsb = (uint32_t)__cvta_generic_to_shared(&Bs[0][0]);

#define ISSUE_CHUNK(CH, BUF) do {                                            \
        const uint32_t ab = asb + (BUF) * 8192 + lrow * 128;                 \
        const uint32_t bb = bsb + (BUF) * 8192 + lrow * 128;                 \
        cpasync16(ab + usw0 * 16, Xrow + (CH) * 16 + lq * 2);                \
        cpasync16(ab + usw1 * 16, Xrow + (CH) * 16 + (lq + 4) * 2);          \
        cpasync16(bb + usw0 * 16, Wrow + (CH) * 16 + lq * 2);                \
        cpasync16(bb + usw1 * 16, Wrow + (CH) * 16 + (lq + 4) * 2);          \
        asm volatile("cp.async.commit_group;");                              \
    } while (0)

    float acc[4][4];
#pragma unroll
    for (int nt = 0; nt < 4; nt++)
#pragma unroll
        for (int e = 0; e < 4; e++) acc[nt][e] = 0.0f;

    ISSUE_CHUNK(0, 0);

    for (int ch = 0; ch < nc; ch++) {
        if (ch + 1 < nc) {
            ISSUE_CHUNK(ch + 1, (ch + 1) & 1);
            asm volatile("cp.async.wait_group 1;");
        } else {
            asm volatile("cp.async.wait_group 0;");
        }
        __syncthreads();

        const float* Ab = As[ch & 1];
        const float* Bb = Bs[ch & 1];
#pragma unroll
        for (int ks = 0; ks < 2; ks++) {
            const int kb = ks * 8;
            const float2 a0 = *(const float2*)&Ab[(m0 + g) * 32 + 2 * ((kb + cc) ^ sw)];
            const float2 a1 = *(const float2*)&Ab[(m0 + g + 8) * 32 + 2 * ((kb + cc) ^ sw)];
            const float2 a2 = *(const float2*)&Ab[(m0 + g) * 32 + 2 * ((kb + cc + 4) ^ sw)];
            const float2 a3 = *(const float2*)&Ab[(m0 + g + 8) * 32 + 2 * ((kb + cc + 4) ^ sw)];
            const uint32_t ahi[4] = {__float_as_uint(a0.x), __float_as_uint(a1.x),
                                     __float_as_uint(a2.x), __float_as_uint(a3.x)};
            const uint32_t alo[4] = {__float_as_uint(a0.y), __float_as_uint(a1.y),
                                     __float_as_uint(a2.y), __float_as_uint(a3.y)};
#pragma unroll
            for (int nt = 0; nt < 4; nt++) {
                const int rn = n0 + nt * 8 + g;
                const float2 b0 = *(const float2*)&Bb[rn * 32 + 2 * ((kb + cc) ^ sw)];
                const float2 b1 = *(const float2*)&Bb[rn * 32 + 2 * ((kb + cc + 4) ^ sw)];
                const uint32_t bhi[2] = {__float_as_uint(b0.x), __float_as_uint(b1.x)};
                const uint32_t blo[2] = {__float_as_uint(b0.y), __float_as_uint(b1.y)};
                mma_tf32(acc[nt], ahi, bhi);
                mma_tf32(acc[nt], ahi, blo);
                mma_tf32(acc[nt], alo, bhi);
            }
        }
        __syncthreads();
    }

    const int row0 = bm * 64 + m0 + g;
#pragma unroll
    for (int nt = 0; nt < 4; nt++) {
        const int col = bn * 64 + n0 + nt * 8 + cc * 2;
        *(float2*)&Y[row0 * DM + col] = make_float2(acc[nt][0], acc[nt][1]);
        *(float2*)&Y[(row0 + 8) * DM + col] = make_float2(acc[nt][2], acc[nt][3]);
    }
#undef ISSUE_CHUNK
}

// ---------------- tropical linear + partial reduce + activation ---------------
__global__ __launch_bounds__(256) void k_trop(const float* __restrict__ Wqt,
                                              const float* __restrict__ Wkt,
                                              const float* __restrict__ Wvt,
                                              const float* __restrict__ lam)
{
    __shared__ float Wts[64][65];
    __shared__ float ar[16][65];

    const int gemm = blockIdx.z;
    const float* Wt = (gemm == 0) ? Wqt : ((gemm == 1) ? Wkt : Wvt);
    float* out = (gemm == 0) ? g_Q : ((gemm == 1) ? g_K : g_V);
    const int bh = blockIdx.y;
    const int b = bh >> 3, h = bh & 7;
    const int l0 = blockIdx.x * 16;
    const int tid = threadIdx.x;

    for (int idx = tid; idx < 64 * 64; idx += 256) {
        const int o = idx >> 6, i = idx & 63;
        Wts[i][o] = Wt[idx];
    }
    for (int idx = tid; idx < 16 * 64; idx += 256) {
        const int r = idx >> 6, i = idx & 63;
        const int gidx = (b * LSEQ + l0 + r) * DM + h * DK + i;
        const float* p = g_pp + gemm * 2 * (BL * DM) + gidx;
        const float s = p[0] + p[BL * DM];
        ar[r][i] = log1pf(fmaxf(s, 0.0f)) - lam[h * DK + i];
    }
    __syncthreads();

    const int o = tid & 63, rg = tid >> 6;
    float m[4] = {NEG_BIG, NEG_BIG, NEG_BIG, NEG_BIG};
#pragma unroll 8
    for (int i = 0; i < 64; i++) {
        const float wv = Wts[i][o];
#pragma unroll
        for (int rr = 0; rr < 4; rr++)
            m[rr] = fmaxf(m[rr], ar[rg * 4 + rr][i] + wv);
    }
#pragma unroll
    for (int rr = 0; rr < 4; rr++)
        out[(bh * LSEQ + l0 + rg * 4 + rr) * DK + o] = m[rr];
}

// ---------------- fused scores + partial context (32i x 32j tiles) ------------
// Grid (8 it, 8 jt, 16 bh) = 1024 blocks, 256 threads.
// Phase A: per-thread 4i x 1j. Phase B: per-thread 4i x 2d (scalar, R14 form).
// Kt buffer dead after phase A; reused for the Ss tile.
__global__ __launch_bounds__(256, 6) void k_scores_ctx(float* __restrict__ scores)
{
    __shared__ float Qs[32][68];
    __shared__ float KtSs[64 * 34];  // phase A: Kt[d][j] stride 34; then Ss[j][i] stride 33
    __shared__ float Vs[32][68];

    const int it = blockIdx.x, jt = blockIdx.y, bh = blockIdx.z;
    const int i0 = it * 32, j0 = jt * 32;
    const int tid = threadIdx.x;
    const int lane = tid & 31;
    const int w = tid >> 5;
    const int ia = w * 4;            // this thread's 4 i rows
    const int ja = lane;             // phase-A single j col

    // load Q tile (32 x 64)
    {
#pragma unroll
        for (int t = 0; t < 2; t++) {
            const int idx = tid + t * 256;
            const int r = idx >> 4, dq = (idx & 15) * 4;
            *(float4*)&Qs[r][dq] = *(const float4*)&g_Q[(bh * LSEQ + i0 + r) * DK + dq];
        }
    }
    // load K (transposed, 32 j) and V tiles
    {
        const float4* Kp = (const float4*)(g_K + (bh * LSEQ + j0) * DK);
        const float4* Vp = (const float4*)(g_V + (bh * LSEQ + j0) * DK);
#pragma unroll
        for (int t = 0; t < 2; t++) {
            const int idx = tid + t * 256;           // 0..511
            const int j = idx >> 4, d4 = (idx & 15) * 4;
            const float4 kv = Kp[idx];
            KtSs[(d4 + 0) * 34 + j] = kv.x; KtSs[(d4 + 1) * 34 + j] = kv.y;
            KtSs[(d4 + 2) * 34 + j] = kv.z; KtSs[(d4 + 3) * 34 + j] = kv.w;
            *(float4*)&Vs[j][d4] = Vp[idx];
        }
    }
    __syncthreads();

    // ---- phase A: 4i x 1j scores ----
    float s[4];
    {
        float mx[4], mn[4];
#pragma unroll
        for (int a = 0; a < 4; a++) { mx[a] = NEG_BIG; mn[a] = POS_BIG; }
#pragma unroll
        for (int t = 0; t < 16; t++) {
            float4 q[4];
#pragma unroll
            for (int a = 0; a < 4; a++)
                q[a] = *(const float4*)&Qs[ia + a][t * 4];   // broadcast
#pragma unroll
            for (int e = 0; e < 4; e++) {
                const float kd = KtSs[(t * 4 + e) * 34 + ja];   // lane-consecutive
#pragma unroll
                for (int a = 0; a < 4; a++) {
                    const float qe = (e == 0) ? q[a].x : (e == 1) ? q[a].y
                                   : (e == 2) ? q[a].z : q[a].w;
                    const float d = qe - kd;
                    mx[a] = fmaxf(mx[a], d);
                    mn[a] = fminf(mn[a], d);
                }
            }
        }
#pragma unroll
        for (int a = 0; a < 4; a++) {
            s[a] = mn[a] - mx[a];
            scores[(bh * LSEQ + i0 + ia + a) * LSEQ + j0 + ja] = s[a];
        }
    }
    __syncthreads();   // everyone done reading Kt

    // stash scores tile into the (dead) Kt buffer as Ss[j][i], stride 33
#pragma unroll
    for (int a = 0; a < 4; a++)
        KtSs[ja * 33 + ia + a] = s[a];
    __syncthreads();

    // ---- phase B: 4i x 2d partial context over this block's 32 j ----
    {
        const int d0 = lane * 2;
        float acc[4][2];
#pragma unroll
        for (int a = 0; a < 4; a++) { acc[a][0] = NEG_BIG; acc[a][1] = NEG_BIG; }

#pragma unroll 4
        for (int j = 0; j < 32; j += 2) {
            const float2 v0 = *(const float2*)&Vs[j][d0];
            const float2 v1 = *(const float2*)&Vs[j + 1][d0];
#pragma unroll
            for (int a = 0; a < 4; a++) {
                const float sa = KtSs[j * 33 + ia + a];         // broadcast
                const float sb = KtSs[(j + 1) * 33 + ia + a];   // broadcast
                acc[a][0] = fmaxf(acc[a][0], sa + v0.x);
                acc[a][1] = fmaxf(acc[a][1], sa + v0.y);
                acc[a][0] = fmaxf(acc[a][0], sb + v1.x);
                acc[a][1] = fmaxf(acc[a][1], sb + v1.y);
            }
        }

        float* cp = g_cp + jt * (BH * LSEQ * DK) + bh * (LSEQ * DK);
#pragma unroll
        for (int a = 0; a < 4; a++)
            *(float2*)&cp[(i0 + ia + a) * DK + d0] = make_float2(acc[a][0], acc[a][1]);
    }
}

// ---------------- ctx finalize: 8-way max + expm1 + tf32 split ----------------
__global__ __launch_bounds__(256) void k_ctxfin()
{
    const int e2 = blockIdx.x * 256 + threadIdx.x;   // float2 index, 131072 total
    const int e = e2 * 2;
    const int bh = e >> 14;
    const int rem = e & 16383;
    const int l = rem >> 6;
    const int d = rem & 63;
    const int b = bh >> 3, h = bh & 7;

    const float2* p = (const float2*)g_cp;
    float2 m = p[e2];
#pragma unroll
    for (int z = 1; z < 8; z++) {
        const float2 t = p[z * 131072 + e2];
        m.x = fmaxf(m.x, t.x);
        m.y = fmaxf(m.y, t.y);
    }
    const float vx = expm1f(m.x);
    const float vy = expm1f(m.y);
    const float hx = tf32r(vx), hy = tf32r(vy);
    *(float4*)&g_ctxs[(b * LSEQ + l) * DM + h * DK + d] =
        make_float4(hx, tf32r(vx - hx), hy, tf32r(vy - hy));
}

// ---------------- splitK reduce for the output GEMM ---------------------------
__global__ __launch_bounds__(256) void k_reduce(float* __restrict__ out)
{
    const int idx = blockIdx.x * 256 + threadIdx.x;
    const float4* p = (const float4*)g_op;
    float4 s = p[idx];
#pragma unroll
    for (int z = 1; z < 4; z++) {
        const float4 t = p[z * 65536 + idx];
        s.x += t.x; s.y += t.y; s.z += t.z; s.w += t.w;
    }
    ((float4*)out)[idx] = s;
}

// ---------------- launch ------------------------------------------------------
extern "C" void kernel_launch(void* const* d_in, const int* in_sizes, int n_in,
                              void* d_out, int out_size)
{
    const float* x   = (const float*)d_in[0];
    const float* Wq  = (const float*)d_in[1];
    const float* Wk  = (const float*)d_in[2];
    const float* Wv  = (const float*)d_in[3];
    const float* Wo  = (const float*)d_in[4];
    const float* lam = (const float*)d_in[5];
    const float* Wqt = (const float*)d_in[6];
    const float* Wkt = (const float*)d_in[7];
    const float* Wvt = (const float*)d_in[8];
    float* out = (float*)d_out;
    float* scores = out + BL * DM;

    k_split<<<dim3(128, 5), 256>>>(x, Wq, Wk, Wv, Wo);
    k_gemm_tc<<<dim3(8, 8, 6), 256>>>(0);
    k_trop<<<dim3(16, 16, 3), 256>>>(Wqt, Wkt, Wvt, lam);
    k_scores_ctx<<<dim3(8, 8, 16), 256>>>(scores);
    k_ctxfin<<<512, 256>>>();
    k_gemm_tc<<<dim3(8, 8, 4), 256>>>(1);
    k_reduce<<<256, 256>>>(out);
}